// round 8
// baseline (speedup 1.0000x reference)
#include <cuda_runtime.h>
#include <cstdint>

#define T_STEPS 512
#define BD 64
#define ID 256
#define HD 1024
#define OD 256
#define NG 4096
#define KD 1280
#define NPC 32
#define NCTA 136
#define NCHUNK 20
#define NKI 160                         // KD / 8

#define SW_FLOATS (NKI * 2 * 32 * 4)    // 40960 floats = 160KB (W fragments)
#define SRED_FLOATS (8 * 64 * 17)       // 8704 floats (reduction buffer)
#define SMEM_BYTES ((SW_FLOATS + SRED_FLOATS) * 4)   // 198656 B
#define RED_PITCH 17

// Persistent device scratch. x and h live in GLOBAL MEMORY in MMA-fragment-
// blocked layout: 512-float blocks, one per (timestep-or-h, 8-column group);
// lane l = G*4+tg owns floats [l*64, l*64+64): 4 float4s =
// {m0:(rG c tg, rG c tg+4, rG+8 c tg, rG+8 c tg+4), m1: rows+16, ...}.
__device__ float g_xr[(size_t)T_STEPS * BD * ID];  // [T][32 blocks][512]
__device__ float g_h[2][BD * HD];                  // [128 blocks][512] ping-pong
__device__ unsigned g_arrive;                      // grid barrier counter

// float offset of (row 0..63, within-group col cg 0..7) inside a 512 block
__device__ __forceinline__ int frag_off(int row, int cg) {
    return (row & 7) * 64 + (cg & 3) * 16 + ((row >> 4) * 2 + ((row >> 3) & 1)) * 2 + (cg >> 2);
}

__device__ __forceinline__ uint32_t f2tf(float f) {
    uint32_t u;
    asm("cvt.rna.tf32.f32 %0, %1;" : "=r"(u) : "f"(f));
    return u;
}
__device__ __forceinline__ float f2tff(float f) { return __uint_as_float(f2tf(f)); }

// ---------------------------------------------------------------------------
// Prep: x -> tf32-rounded fragment-blocked copy; zero h; reset barrier.
// ---------------------------------------------------------------------------
__global__ void prep_kernel(const float* __restrict__ x)
{
    const size_t S_X = (size_t)T_STEPS * BD * ID;
    const size_t S_H = S_X + 2 * BD * HD;
    for (size_t i = (size_t)blockIdx.x * blockDim.x + threadIdx.x; i < S_H;
         i += (size_t)gridDim.x * blockDim.x) {
        if (i == 0) g_arrive = 0;
        if (i < S_X) {
            int c = (int)(i % ID);
            int b = (int)((i / ID) % BD);
            size_t t = i / (BD * ID);
            g_xr[(t * 32 + (c >> 3)) * 512 + frag_off(b, c & 7)] = f2tff(x[i]);
        } else {
            ((float*)g_h)[i - S_X] = 0.0f;
        }
    }
}

// ---------------------------------------------------------------------------
// Persistent LSTM. 136 CTAs x 256 threads (8 warps), one CTA per SM.
// CTA b: gate rows [32b,32b+32) (r = 4*j+gate) or output rows (b>=128).
// Mainloop: NO smem staging — warp w's A fragments for chunk kc are 4
// coalesced LDG.128 from the fragment-blocked x/h, ring of 4 register slots,
// distance-2 prefetch. W fragments resident in smem (2 LDS.128/chunk).
// Next step's x-only chunks preloaded into registers BEFORE the grid barrier.
// ---------------------------------------------------------------------------
__global__ void __launch_bounds__(256, 1) lstm_kernel(
    const float* __restrict__ W_ih, const float* __restrict__ W_hh,
    const float* __restrict__ b_ih, const float* __restrict__ b_hh,
    const float* __restrict__ W_out, const float* __restrict__ b_out,
    float* __restrict__ out)
{
    extern __shared__ float sm[];
    float* sW   = sm;                  // [NKI][2][32 lanes][4] fragment layout
    float* sRed = sm + SW_FLOATS;      // [8 warps][64 rows][RED_PITCH]

    const int tid = threadIdx.x;
    const int lane = tid & 31, w = tid >> 5;
    const int G = lane >> 2, tg = lane & 3;
    const int n0 = blockIdx.x * NPC;
    const bool is_out = (n0 >= NG);

    // ---- Build W fragments in smem (once). Coalesced float4 row reads. ----
    {
        const int r = tid >> 3;                 // local row 0..31
        const int cth = tid & 7;
        const int rowg = n0 + r;
        const int nt = r >> 3, Gr = r & 7;
#pragma unroll 1
        for (int u = 0; u < KD / 32; u++) {
            int col0 = cth * 4 + u * 32;
            float4 v;
            if (rowg < NG) {
                int orig = (rowg & 3) * HD + (rowg >> 2);   // PyTorch i,f,g,o blocks
                if (col0 < ID) v = *(const float4*)&W_ih[(size_t)orig * ID + col0];
                else           v = *(const float4*)&W_hh[(size_t)orig * HD + (col0 - ID)];
            } else {
                if (col0 < ID) v = make_float4(0.f, 0.f, 0.f, 0.f);
                else           v = *(const float4*)&W_out[(size_t)(rowg - NG) * HD + (col0 - ID)];
            }
            float vv[4] = {v.x, v.y, v.z, v.w};
#pragma unroll
            for (int e = 0; e < 4; e++) {
                int col = col0 + e;
                int ki = col >> 3, cw = col & 7;
                int tgc = cw & 3, half = cw >> 2;
                int idx = ((ki * 2 + (nt >> 1)) * 32 + (Gr * 4 + tgc)) * 4 + (nt & 1) * 2 + half;
                sW[idx] = f2tff(vv[e]);
            }
        }
    }

    // ---- Per-thread epilogue bias: thread (b=tid>>2, u=tid&3), cols 4u+g ----
    float bias[2][4];
#pragma unroll
    for (int hn = 0; hn < 2; hn++) {
#pragma unroll
        for (int g = 0; g < 4; g++) {
            int rr = n0 + hn * 16 + 4 * (tid & 3) + g;
            float bv;
            if (rr < NG) {
                int orig = (rr & 3) * HD + (rr >> 2);
                bv = b_ih[orig] + b_hh[orig];
            } else bv = b_out[rr - NG];
            bias[hn][g] = bv;
        }
    }
    float cstate[2] = {0.0f, 0.0f};
    __syncthreads();

    // ---- Register A ring: 4 slots x 4 float4 (lane's 64B per chunk) ----
    float4 Aq[4][4];
    auto slotload = [&](float4* q, int kci, int txL, const float* __restrict__ hsrcL) {
        const int kiG = kci * 8 + w;
        const float4* base = (kiG < 32)
            ? (const float4*)&g_xr[((size_t)txL * 32 + kiG) * 512]
            : (const float4*)&hsrcL[(size_t)(kiG - 32) * 512];
#pragma unroll
        for (int i = 0; i < 4; i++) q[i] = __ldcg(&base[lane * 4 + i]);
    };

    // Initial preload for step 0 (chunks 0,1 are x-only)
    slotload(Aq[0], 0, 0, g_h[0]);
    slotload(Aq[1], 1, 0, g_h[0]);

    // ---- Time loop ----
    for (int t = 0; t <= T_STEPS; t++) {
        const bool active = is_out ? (t > 0) : (t < T_STEPS);
        if (active) {
            const int tx = (t < T_STEPS) ? t : (T_STEPS - 1);  // W=0 on x-range for out rows
            const float* __restrict__ hsrc = g_h[t & 1];

            float acc[4][4][4];
#pragma unroll
            for (int m = 0; m < 4; m++)
#pragma unroll
                for (int n = 0; n < 4; n++)
#pragma unroll
                    for (int e = 0; e < 4; e++) acc[m][n][e] = 0.0f;

            // ---- mainloop: no syncs, no smem staging ----
#pragma unroll 1
            for (int ku = 0; ku < 5; ku++) {
#pragma unroll
                for (int j = 0; j < 4; j++) {
                    const int kci = ku * 4 + j;
                    if (kci + 2 < NCHUNK)
                        slotload(Aq[(j + 2) & 3], kci + 2, tx, hsrc);
                    const int kiG = kci * 8 + w;
                    float4 B0 = *(const float4*)&sW[((kiG * 2 + 0) * 32 + lane) * 4];
                    float4 B1 = *(const float4*)&sW[((kiG * 2 + 1) * 32 + lane) * 4];
#pragma unroll
                    for (int m = 0; m < 4; m++) {
                        uint32_t a0 = __float_as_uint(Aq[j][m].x);
                        uint32_t a2 = __float_as_uint(Aq[j][m].y);
                        uint32_t a1 = __float_as_uint(Aq[j][m].z);
                        uint32_t a3 = __float_as_uint(Aq[j][m].w);
#define MMA1(ACC, B0R, B1R)                                                     \
    asm volatile(                                                               \
        "mma.sync.aligned.m16n8k8.row.col.f32.tf32.tf32.f32 "                   \
        "{%0,%1,%2,%3},{%4,%5,%6,%7},{%8,%9},{%0,%1,%2,%3};"                    \
        : "+f"(ACC[0]), "+f"(ACC[1]), "+f"(ACC[2]), "+f"(ACC[3])                \
        : "r"(a0), "r"(a1), "r"(a2), "r"(a3), "r"(B0R), "r"(B1R))
                        MMA1(acc[m][0], __float_as_uint(B0.x), __float_as_uint(B0.y));
                        MMA1(acc[m][1], __float_as_uint(B0.z), __float_as_uint(B0.w));
                        MMA1(acc[m][2], __float_as_uint(B1.x), __float_as_uint(B1.y));
                        MMA1(acc[m][3], __float_as_uint(B1.z), __float_as_uint(B1.w));
#undef MMA1
                    }
                }
            }

            // ---- 8-way reduction + epilogue, two N-halves of 16 cols ----
            // (scatter regions are per-warp disjoint; sync only before reads)
            const int b = tid >> 2, u = tid & 3;
#pragma unroll 1
            for (int hn = 0; hn < 2; hn++) {
#pragma unroll
                for (int m = 0; m < 4; m++)
#pragma unroll
                    for (int nl = 0; nl < 2; nl++)
#pragma unroll
                        for (int e = 0; e < 4; e++) {
                            int row = 16 * m + G + (e >> 1) * 8;
                            int ch = nl * 8 + 2 * tg + (e & 1);
                            sRed[(w * BD + row) * RED_PITCH + ch] = acc[m][2 * hn + nl][e];
                        }
                __syncthreads();
                float gv[4];
#pragma unroll
                for (int g = 0; g < 4; g++) {
                    float s = 0.0f;
#pragma unroll
                    for (int ww = 0; ww < 8; ww++)
                        s += sRed[(ww * BD + b) * RED_PITCH + 4 * u + g];
                    gv[g] = s + bias[hn][g];
                }
                if (!is_out) {
                    float ig = 1.0f / (1.0f + __expf(-gv[0]));
                    float fg = 1.0f / (1.0f + __expf(-gv[1]));
                    float gg = tanhf(gv[2]);
                    float og = 1.0f / (1.0f + __expf(-gv[3]));
                    float cv = fg * cstate[hn] + ig * gg;
                    cstate[hn] = cv;
                    int jl = 4 * hn + u;
                    // fragment-blocked h store: CTA's 8 units = block blockIdx.x
                    g_h[(t + 1) & 1][blockIdx.x * 512 + frag_off(b, jl)] =
                        f2tff(og * tanhf(cv));
                } else {
                    float* __restrict__ dst = out + (size_t)(t - 1) * BD * OD;
                    int col = (n0 - NG) + hn * 16 + 4 * u;
                    *(float4*)&dst[(size_t)b * OD + col] =
                        make_float4(gv[0], gv[1], gv[2], gv[3]);
                }
                __syncthreads();
            }
        }

        if (t == T_STEPS) break;

        // ---- preload next step's x-only chunks (0,1) BEFORE barrier ----
        {
            int txn = (t + 1 < T_STEPS) ? (t + 1) : (T_STEPS - 1);
            slotload(Aq[0], 0, txn, g_h[0]);
            slotload(Aq[1], 1, txn, g_h[0]);
        }

        // ---- grid barrier (136 CTAs co-resident) ----
        __syncthreads();
        if (tid == 0) {
            __threadfence();
            atomicAdd(&g_arrive, 1u);
            const unsigned target = (unsigned)(t + 1) * NCTA;
            unsigned v;
            do {
                asm volatile("ld.acquire.gpu.u32 %0, [%1];" : "=r"(v) : "l"(&g_arrive));
            } while (v < target);
        }
        __syncthreads();
    }
}

// ---------------------------------------------------------------------------
extern "C" void kernel_launch(void* const* d_in, const int* in_sizes, int n_in,
                              void* d_out, int out_size)
{
    const float* x     = (const float*)d_in[0];
    const float* W_ih  = (const float*)d_in[1];
    const float* W_hh  = (const float*)d_in[2];
    const float* b_ih  = (const float*)d_in[3];
    const float* b_hh  = (const float*)d_in[4];
    const float* W_out = (const float*)d_in[5];
    const float* b_out = (const float*)d_in[6];
    float* out = (float*)d_out;

    cudaFuncSetAttribute(lstm_kernel,
                         cudaFuncAttributeMaxDynamicSharedMemorySize, SMEM_BYTES);
    prep_kernel<<<1024, 256>>>(x);
    lstm_kernel<<<NCTA, 256, SMEM_BYTES>>>(W_ih, W_hh, b_ih, b_hh, W_out, b_out, out);
}

// round 9
// speedup vs baseline: 1.8718x; 1.8718x over previous
#include <cuda_runtime.h>
#include <cstdint>

#define T_STEPS 512
#define BD 64
#define ID 256
#define HD 1024
#define OD 256
#define NG 4096
#define KD 1280
#define NPC 32
#define NCTA 136
#define NW 16                           // warps per CTA
#define NCHUNK 10                       // K chunks of 128 (16 k8-slices)
#define NKI 160                         // KD / 8
#define NBUF 2

#define SW_FLOATS (NKI * 2 * 32 * 4)    // 40960 floats = 160KB (W fragments)
#define SS_FLOATS (NW * NBUF * BD * 8)  // 16384 floats = 64KB (slices; reused as sRed)
#define SMEM_BYTES ((SW_FLOATS + SS_FLOATS) * 4)   // 229376 B
#define RED_PITCH 17

// Persistent device scratch (allocation-free rule: __device__ globals)
__device__ float g_xr[(size_t)T_STEPS * BD * ID];  // tf32-rounded x, pair-packed within 8-groups
__device__ float g_h[2][BD * HD];                  // ping-pong hidden state (rounded, pair-packed)
__device__ unsigned g_arrive;                      // grid barrier counter

__device__ __forceinline__ uint32_t f2tf(float f) {
    uint32_t u;
    asm("cvt.rna.tf32.f32 %0, %1;" : "=r"(u) : "f"(f));
    return u;
}
__device__ __forceinline__ float f2tff(float f) { return __uint_as_float(f2tf(f)); }

__device__ __forceinline__ void cpasync16(uint32_t smem, const void* gmem) {
    asm volatile("cp.async.cg.shared.global [%0], [%1], 16;\n" :: "r"(smem), "l"(gmem));
}

// ---------------------------------------------------------------------------
// Prep: rounded+permuted x copy, zero h, reset barrier counter.
// Pair-pack permutation WITHIN each 8-group: offset cg -> 2*(cg&3) + (cg>>2).
// ---------------------------------------------------------------------------
__global__ void prep_kernel(const float* __restrict__ x)
{
    const size_t S_X = (size_t)T_STEPS * BD * ID;
    const size_t S_H = S_X + 2 * BD * HD;
    for (size_t i = (size_t)blockIdx.x * blockDim.x + threadIdx.x; i < S_H;
         i += (size_t)gridDim.x * blockDim.x) {
        if (i == 0) g_arrive = 0;
        if (i < S_X) {
            int c = (int)(i & 255);             // ID == 256
            int cg = c & 7;
            size_t base = i - (size_t)c;
            g_xr[base + (c & ~7) + 2 * (cg & 3) + (cg >> 2)] = f2tff(x[i]);
        } else {
            ((float*)g_h)[i - S_X] = 0.0f;
        }
    }
}

// ---------------------------------------------------------------------------
// Persistent LSTM. 136 CTAs x 512 threads (16 warps), one CTA per SM.
// CTA b: gate rows [32b,32b+32) (r = 4*j+gate) or output rows (b>=128).
// 16-WAY K-SPLIT: warp w owns k8-slices {c*16+w, c<10}; per-warp cp.async
// staging (NBUF=2), no block syncs in the mainloop, 10-chunk serial chain
// (half of R7) with 4 warps/SMSP for latency hiding.
// ---------------------------------------------------------------------------
__global__ void __launch_bounds__(512, 1) lstm_kernel(
    const float* __restrict__ W_ih, const float* __restrict__ W_hh,
    const float* __restrict__ b_ih, const float* __restrict__ b_hh,
    const float* __restrict__ W_out, const float* __restrict__ b_out,
    float* __restrict__ out)
{
    extern __shared__ float sm[];
    float* sW = sm;                    // [NKI][2][32 lanes][4]  (fragment layout)
    float* sS = sm + SW_FLOATS;        // [16 warps][NBUF][64 rows][8]; reused as sRed

    const int tid = threadIdx.x;
    const int lane = tid & 31, w = tid >> 5;
    const int G = lane >> 2, tg = lane & 3;
    const int n0 = blockIdx.x * NPC;
    const bool is_out = (n0 >= NG);

    // ---- Build W fragments in smem (once). Coalesced float4 row reads. ----
    {
        const int r = tid >> 4;                 // local row 0..31
        const int cth = tid & 15;
        const int rowg = n0 + r;
        const int nt = r >> 3, Gr = r & 7;
#pragma unroll 1
        for (int u = 0; u < KD / 64; u++) {
            int col0 = cth * 4 + u * 64;
            float4 v;
            if (rowg < NG) {
                int orig = (rowg & 3) * HD + (rowg >> 2);   // PyTorch i,f,g,o blocks
                if (col0 < ID) v = *(const float4*)&W_ih[(size_t)orig * ID + col0];
                else           v = *(const float4*)&W_hh[(size_t)orig * HD + (col0 - ID)];
            } else {
                if (col0 < ID) v = make_float4(0.f, 0.f, 0.f, 0.f);
                else           v = *(const float4*)&W_out[(size_t)(rowg - NG) * HD + (col0 - ID)];
            }
            float vv[4] = {v.x, v.y, v.z, v.w};
#pragma unroll
            for (int e = 0; e < 4; e++) {
                int col = col0 + e;
                int ki = col >> 3, cw = col & 7;
                int tgc = cw & 3, half = cw >> 2;
                int idx = ((ki * 2 + (nt >> 1)) * 32 + (Gr * 4 + tgc)) * 4 + (nt & 1) * 2 + half;
                sW[idx] = f2tff(vv[e]);
            }
        }
    }

    // ---- Per-thread epilogue bias (used by threads < 256): cols 4u+g ----
    float bias[2][4];
#pragma unroll
    for (int hn = 0; hn < 2; hn++) {
#pragma unroll
        for (int g = 0; g < 4; g++) {
            int rr = n0 + hn * 16 + 4 * (tid & 3) + g;
            float bv;
            if (rr < NG) {
                int orig = (rr & 3) * HD + (rr >> 2);
                bv = b_ih[orig] + b_hh[orig];
            } else bv = b_out[rr - NG];
            bias[hn][g] = bv;
        }
    }
    float cstate[2] = {0.0f, 0.0f};
    __syncthreads();

    // ---- Per-warp staging: chunk c's 64x8 slice for this warp ----
    auto stageS = [&](int c, int tx, const float* __restrict__ hsrc) {
        const int kiG = c * NW + w;
        float* dstb = sS + (size_t)(w * NBUF + (c & 1)) * BD * 8;
        const float* srcb;
        int rstride;
        if (kiG < 32) { srcb = &g_xr[(size_t)tx * BD * ID + kiG * 8]; rstride = ID; }
        else          { srcb = hsrc + (kiG * 8 - ID);                 rstride = HD; }
#pragma unroll
        for (int it = 0; it < 4; it++) {
            int seg = it * 32 + lane;
            int row = seg >> 1, half = seg & 1;
            cpasync16((uint32_t)__cvta_generic_to_shared(dstb + row * 8 + half * 4),
                      srcb + (size_t)row * rstride + half * 4);
        }
    };

    // Initial prefetch for step 0 (chunk 0 is x-only: slices 0..15 < 32)
    if (!is_out) {
        stageS(0, 0, g_h[0]);
        asm volatile("cp.async.commit_group;");
    }

    // ---- Time loop ----
    for (int t = 0; t <= T_STEPS; t++) {
        const bool active = is_out ? (t > 0) : (t < T_STEPS);
        if (active) {
            const int tx = (t < T_STEPS) ? t : (T_STEPS - 1);  // W=0 on x-range for out rows
            const float* __restrict__ hsrc = g_h[t & 1];

            float acc[4][4][4];
#pragma unroll
            for (int m = 0; m < 4; m++)
#pragma unroll
                for (int n = 0; n < 4; n++)
#pragma unroll
                    for (int e = 0; e < 4; e++) acc[m][n][e] = 0.0f;

            // ---- decoupled mainloop: NO __syncthreads, per-warp groups ----
#pragma unroll 1
            for (int c = 0; c < NCHUNK; c++) {
                if (c + 1 < NCHUNK) {
                    stageS(c + 1, tx, hsrc);
                    asm volatile("cp.async.commit_group;");
                    asm volatile("cp.async.wait_group 1;");
                } else {
                    asm volatile("cp.async.wait_group 0;");
                }
                __syncwarp();
                const float* buf = sS + (size_t)(w * NBUF + (c & 1)) * BD * 8;
                const int kiG = c * NW + w;
                float4 B0 = *(const float4*)&sW[((kiG * 2 + 0) * 32 + lane) * 4];
                float4 B1 = *(const float4*)&sW[((kiG * 2 + 1) * 32 + lane) * 4];
#pragma unroll
                for (int m = 0; m < 4; m++) {
                    float2 aL = *(const float2*)&buf[(16 * m + G) * 8 + 2 * tg];
                    float2 aH = *(const float2*)&buf[(16 * m + G + 8) * 8 + 2 * tg];
                    uint32_t a0 = __float_as_uint(aL.x), a2 = __float_as_uint(aL.y);
                    uint32_t a1 = __float_as_uint(aH.x), a3 = __float_as_uint(aH.y);
#define MMA1(ACC, B0R, B1R)                                                     \
    asm volatile(                                                               \
        "mma.sync.aligned.m16n8k8.row.col.f32.tf32.tf32.f32 "                   \
        "{%0,%1,%2,%3},{%4,%5,%6,%7},{%8,%9},{%0,%1,%2,%3};"                    \
        : "+f"(ACC[0]), "+f"(ACC[1]), "+f"(ACC[2]), "+f"(ACC[3])                \
        : "r"(a0), "r"(a1), "r"(a2), "r"(a3), "r"(B0R), "r"(B1R))
                    MMA1(acc[m][0], __float_as_uint(B0.x), __float_as_uint(B0.y));
                    MMA1(acc[m][1], __float_as_uint(B0.z), __float_as_uint(B0.w));
                    MMA1(acc[m][2], __float_as_uint(B1.x), __float_as_uint(B1.y));
                    MMA1(acc[m][3], __float_as_uint(B1.z), __float_as_uint(B1.w));
#undef MMA1
                }
            }
            __syncthreads();    // all warps done with slice buffers before sRed reuse

            // ---- 16-way reduction + epilogue, two N-halves of 16 cols ----
            // Phase 1: warps 0-7 scatter; Phase 2: warps 8-15 add in;
            // Phase 3: threads<256 gather 8 regions + LSTM/out.
            float* sRed = sS;
            const int b = tid >> 2, u = tid & 3;
#pragma unroll 1
            for (int hn = 0; hn < 2; hn++) {
                if (w < 8) {
#pragma unroll
                    for (int m = 0; m < 4; m++)
#pragma unroll
                        for (int nl = 0; nl < 2; nl++)
#pragma unroll
                            for (int e = 0; e < 4; e++) {
                                int row = 16 * m + G + (e >> 1) * 8;
                                int ch = nl * 8 + 2 * tg + (e & 1);
                                sRed[(w * BD + row) * RED_PITCH + ch] = acc[m][2 * hn + nl][e];
                            }
                }
                __syncthreads();
                if (w >= 8) {
#pragma unroll
                    for (int m = 0; m < 4; m++)
#pragma unroll
                        for (int nl = 0; nl < 2; nl++)
#pragma unroll
                            for (int e = 0; e < 4; e++) {
                                int row = 16 * m + G + (e >> 1) * 8;
                                int ch = nl * 8 + 2 * tg + (e & 1);
                                int idx = ((w - 8) * BD + row) * RED_PITCH + ch;
                                sRed[idx] += acc[m][2 * hn + nl][e];
                            }
                }
                __syncthreads();
                if (tid < 256) {
                    float gv[4];
#pragma unroll
                    for (int g = 0; g < 4; g++) {
                        float s = 0.0f;
#pragma unroll
                        for (int ww = 0; ww < 8; ww++)
                            s += sRed[(ww * BD + b) * RED_PITCH + 4 * u + g];
                        gv[g] = s + bias[hn][g];
                    }
                    if (!is_out) {
                        float ig = 1.0f / (1.0f + __expf(-gv[0]));
                        float fg = 1.0f / (1.0f + __expf(-gv[1]));
                        float gg = tanhf(gv[2]);
                        float og = 1.0f / (1.0f + __expf(-gv[3]));
                        float cv = fg * cstate[hn] + ig * gg;
                        cstate[hn] = cv;
                        int jl = 4 * hn + u;
                        int jbase = n0 >> 2;
                        g_h[(t + 1) & 1][b * HD + jbase + 2 * (jl & 3) + (jl >> 2)] =
                            f2tff(og * tanhf(cv));
                    } else {
                        float* __restrict__ dst = out + (size_t)(t - 1) * BD * OD;
                        int col = (n0 - NG) + hn * 16 + 4 * u;
                        *(float4*)&dst[(size_t)b * OD + col] =
                            make_float4(gv[0], gv[1], gv[2], gv[3]);
                    }
                }
                __syncthreads();
            }
        }

        if (t == T_STEPS) break;

        // ---- prefetch next step's x-only chunk 0 BEFORE barrier spin ----
        const bool nact = is_out ? true : (t + 1 < T_STEPS);
        if (nact) {
            int txn = (t + 1 < T_STEPS) ? (t + 1) : (T_STEPS - 1);
            stageS(0, txn, g_h[0]);
            asm volatile("cp.async.commit_group;");
        }

        // ---- grid barrier (136 CTAs co-resident) ----
        __syncthreads();
        if (tid == 0) {
            asm volatile("red.release.gpu.global.add.u32 [%0], 1;"
                         :: "l"(&g_arrive) : "memory");
            const unsigned target = (unsigned)(t + 1) * NCTA;
            unsigned v;
            do {
                asm volatile("ld.acquire.gpu.u32 %0, [%1];" : "=r"(v) : "l"(&g_arrive));
            } while (v < target);
        }
        __syncthreads();
    }
}

// ---------------------------------------------------------------------------
extern "C" void kernel_launch(void* const* d_in, const int* in_sizes, int n_in,
                              void* d_out, int out_size)
{
    const float* x     = (const float*)d_in[0];
    const float* W_ih  = (const float*)d_in[1];
    const float* W_hh  = (const float*)d_in[2];
    const float* b_ih  = (const float*)d_in[3];
    const float* b_hh  = (const float*)d_in[4];
    const float* W_out = (const float*)d_in[5];
    const float* b_out = (const float*)d_in[6];
    float* out = (float*)d_out;

    cudaFuncSetAttribute(lstm_kernel,
                         cudaFuncAttributeMaxDynamicSharedMemorySize, SMEM_BYTES);
    prep_kernel<<<1024, 256>>>(x);
    lstm_kernel<<<NCTA, 512, SMEM_BYTES>>>(W_ih, W_hh, b_ih, b_hh, W_out, b_out, out);
}

// round 10
// speedup vs baseline: 2.4782x; 1.3240x over previous
#include <cuda_runtime.h>
#include <cstdint>

#define T_STEPS 512
#define BD 64
#define ID 256
#define HD 1024
#define OD 256
#define NG 4096
#define KD 1280
#define NPC 32
#define NCTA 136
#define NCHUNK 20                       // K chunks of 64 cols (8 k8-slices each)
#define NKI 160                         // KD / 8
#define NSTAGE 3

#define SW_BYTES (NKI * 2 * 32 * 4 * 4) // 163840 (W fragments)
#define SO_MBAR  SW_BYTES               // 3 x 8B mbarriers
#define SO_STAGE (SW_BYTES + 1024)      // 3 x 16KB stage buffers
#define STAGE_BYTES 16384
#define SMEM_BYTES (SO_STAGE + NSTAGE * STAGE_BYTES)   // 214016
#define RED_PITCH 17

// Persistent device scratch. x/h in SLICE-MAJOR layout:
//   g_xr: [T][32 slices][64 rows][8]   (slice = k8-group of x, pair-packed within 8)
//   g_h:  [2][128 slices][64 rows][8]  (slice = 8 hidden units, pair-packed)
// => any 64-col K-chunk (8 slices) is 16KB CONTIGUOUS -> one bulk copy.
__device__ float g_xr[(size_t)T_STEPS * BD * ID];
__device__ float g_h[2][BD * HD];
__device__ unsigned g_arrive;

__device__ __forceinline__ uint32_t f2tf(float f) {
    uint32_t u;
    asm("cvt.rna.tf32.f32 %0, %1;" : "=r"(u) : "f"(f));
    return u;
}
__device__ __forceinline__ float f2tff(float f) { return __uint_as_float(f2tf(f)); }

// ---------------------------------------------------------------------------
// Prep: x -> slice-major, tf32-rounded, pair-packed; zero h; reset barrier.
// ---------------------------------------------------------------------------
__global__ void prep_kernel(const float* __restrict__ x)
{
    const size_t S_X = (size_t)T_STEPS * BD * ID;
    const size_t S_H = S_X + 2 * BD * HD;
    for (size_t i = (size_t)blockIdx.x * blockDim.x + threadIdx.x; i < S_H;
         i += (size_t)gridDim.x * blockDim.x) {
        if (i == 0) g_arrive = 0;
        if (i < S_X) {
            int c = (int)(i & 255);             // ID == 256
            int b = (int)((i >> 8) & 63);
            size_t t = i >> 14;
            int cg = c & 7;
            g_xr[((t * 32 + (c >> 3)) * 64 + b) * 8 + 2 * (cg & 3) + (cg >> 2)] =
                f2tff(x[i]);
        } else {
            ((float*)g_h)[i - S_X] = 0.0f;
        }
    }
}

// ---------------------------------------------------------------------------
// Persistent LSTM. 136 CTAs x 256 threads (8 warps), one CTA per SM.
// CTA b: gate rows [32b,32b+32) (r = 4*j+gate) or output rows (b>=128).
// Staging: ONE cp.async.bulk (16KB) per 64-col chunk, issued by tid 0,
// completion via mbarrier complete_tx; 3 stages; chunks 0-1 (x-only)
// pre-issued before the grid barrier. 8-way K-split compute + reduction.
// ---------------------------------------------------------------------------
__global__ void __launch_bounds__(256, 1) lstm_kernel(
    const float* __restrict__ W_ih, const float* __restrict__ W_hh,
    const float* __restrict__ b_ih, const float* __restrict__ b_hh,
    const float* __restrict__ W_out, const float* __restrict__ b_out,
    float* __restrict__ out)
{
    extern __shared__ __align__(1024) char smc[];
    float* sW = (float*)smc;                       // [NKI][2][32 lanes][4]
    float* sRed = (float*)(smc + SO_STAGE);        // epilogue reuse of stage area
    const uint32_t sb = (uint32_t)__cvta_generic_to_shared(smc);

    const int tid = threadIdx.x;
    const int lane = tid & 31, w = tid >> 5;
    const int G = lane >> 2, tg = lane & 3;
    const int n0 = blockIdx.x * NPC;
    const bool is_out = (n0 >= NG);

    // ---- Build W fragments in smem (once). Coalesced float4 row reads. ----
    {
        const int r = tid >> 3;                 // local row 0..31
        const int cth = tid & 7;
        const int rowg = n0 + r;
        const int nt = r >> 3, Gr = r & 7;
#pragma unroll 1
        for (int u = 0; u < KD / 32; u++) {
            int col0 = cth * 4 + u * 32;
            float4 v;
            if (rowg < NG) {
                int orig = (rowg & 3) * HD + (rowg >> 2);   // PyTorch i,f,g,o blocks
                if (col0 < ID) v = *(const float4*)&W_ih[(size_t)orig * ID + col0];
                else           v = *(const float4*)&W_hh[(size_t)orig * HD + (col0 - ID)];
            } else {
                if (col0 < ID) v = make_float4(0.f, 0.f, 0.f, 0.f);
                else           v = *(const float4*)&W_out[(size_t)(rowg - NG) * HD + (col0 - ID)];
            }
            float vv[4] = {v.x, v.y, v.z, v.w};
#pragma unroll
            for (int e = 0; e < 4; e++) {
                int col = col0 + e;
                int ki = col >> 3, cw = col & 7;
                int tgc = cw & 3, half = cw >> 2;
                int idx = ((ki * 2 + (nt >> 1)) * 32 + (Gr * 4 + tgc)) * 4 + (nt & 1) * 2 + half;
                sW[idx] = f2tff(vv[e]);
            }
        }
    }

    // ---- Per-thread epilogue bias: thread (b=tid>>2, u=tid&3), cols 4u+g ----
    float bias[2][4];
#pragma unroll
    for (int hn = 0; hn < 2; hn++) {
#pragma unroll
        for (int g = 0; g < 4; g++) {
            int rr = n0 + hn * 16 + 4 * (tid & 3) + g;
            float bv;
            if (rr < NG) {
                int orig = (rr & 3) * HD + (rr >> 2);
                bv = b_ih[orig] + b_hh[orig];
            } else bv = b_out[rr - NG];
            bias[hn][g] = bv;
        }
    }
    float cstate[2] = {0.0f, 0.0f};

    if (tid == 0) {
#pragma unroll
        for (int s = 0; s < NSTAGE; s++)
            asm volatile("mbarrier.init.shared.b64 [%0], 1;"
                         :: "r"(sb + SO_MBAR + 8 * s) : "memory");
    }
    __syncthreads();

    int pb[NSTAGE] = {0, 0, 0};        // per-buffer expected parity

    // ---- Bulk staging: one 16KB copy per chunk (tid 0 only) ----
    auto issue = [&](int c, int tx, const float* __restrict__ hsrc) {
        uint32_t dst = sb + SO_STAGE + (uint32_t)((c % 3) * STAGE_BYTES);
        uint32_t m   = sb + SO_MBAR + (uint32_t)((c % 3) * 8);
        const float* src = (c < 4)
            ? &g_xr[((size_t)tx * 32 + c * 8) * 512]
            : &hsrc[(size_t)(c * 8 - 32) * 512];
        asm volatile("mbarrier.arrive.expect_tx.shared.b64 _, [%0], %1;"
                     :: "r"(m), "r"((uint32_t)STAGE_BYTES) : "memory");
        asm volatile(
            "cp.async.bulk.shared::cluster.global.mbarrier::complete_tx::bytes "
            "[%0], [%1], %2, [%3];"
            :: "r"(dst), "l"(src), "r"((uint32_t)STAGE_BYTES), "r"(m) : "memory");
    };
    auto mwait = [&](int bufi) {
        uint32_t m = sb + SO_MBAR + (uint32_t)(bufi * 8);
        uint32_t par = (uint32_t)pb[bufi];
        asm volatile(
            "{\n\t.reg .pred P;\n\tW_%=:\n\t"
            "mbarrier.try_wait.parity.shared.b64 P, [%0], %1;\n\t"
            "@P bra.uni D_%=;\n\tbra.uni W_%=;\n\tD_%=:\n\t}"
            :: "r"(m), "r"(par) : "memory");
        pb[bufi] ^= 1;
    };

    // Initial pre-issue for step 0 (chunks 0,1 are x-only) — gate CTAs only
    if (!is_out && tid == 0) {
        asm volatile("fence.proxy.async;" ::: "memory");
        issue(0, 0, g_h[0]);
        issue(1, 0, g_h[0]);
    }

    // ---- Time loop ----
    for (int t = 0; t <= T_STEPS; t++) {
        const bool active = is_out ? (t > 0) : (t < T_STEPS);
        if (active) {
            const int tx = (t < T_STEPS) ? t : (T_STEPS - 1);  // W=0 on x-range for out rows
            const float* __restrict__ hsrc = g_h[t & 1];

            float acc[4][4][4];
#pragma unroll
            for (int m = 0; m < 4; m++)
#pragma unroll
                for (int n = 0; n < 4; n++)
#pragma unroll
                    for (int e = 0; e < 4; e++) acc[m][n][e] = 0.0f;

#pragma unroll 1
            for (int c = 0; c < NCHUNK; c++) {
                mwait(c % 3);
                const float* buf = (const float*)(smc + SO_STAGE + (c % 3) * STAGE_BYTES)
                                   + w * 512;
                const int kiG = c * 8 + w;          // this warp's k8-slice
                float4 B0 = *(const float4*)&sW[((kiG * 2 + 0) * 32 + lane) * 4];
                float4 B1 = *(const float4*)&sW[((kiG * 2 + 1) * 32 + lane) * 4];
#pragma unroll
                for (int m = 0; m < 4; m++) {
                    float2 aL = *(const float2*)&buf[(16 * m + G) * 8 + 2 * tg];
                    float2 aH = *(const float2*)&buf[(16 * m + G + 8) * 8 + 2 * tg];
                    uint32_t a0 = __float_as_uint(aL.x), a2 = __float_as_uint(aL.y);
                    uint32_t a1 = __float_as_uint(aH.x), a3 = __float_as_uint(aH.y);
#define MMA1(ACC, B0R, B1R)                                                     \
    asm volatile(                                                               \
        "mma.sync.aligned.m16n8k8.row.col.f32.tf32.tf32.f32 "                   \
        "{%0,%1,%2,%3},{%4,%5,%6,%7},{%8,%9},{%0,%1,%2,%3};"                    \
        : "+f"(ACC[0]), "+f"(ACC[1]), "+f"(ACC[2]), "+f"(ACC[3])                \
        : "r"(a0), "r"(a1), "r"(a2), "r"(a3), "r"(B0R), "r"(B1R))
                    MMA1(acc[m][0], __float_as_uint(B0.x), __float_as_uint(B0.y));
                    MMA1(acc[m][1], __float_as_uint(B0.z), __float_as_uint(B0.w));
                    MMA1(acc[m][2], __float_as_uint(B1.x), __float_as_uint(B1.y));
                    MMA1(acc[m][3], __float_as_uint(B1.z), __float_as_uint(B1.w));
#undef MMA1
                }
                __syncthreads();                    // all warps done with buffer c%3
                if (c + 2 < NCHUNK && tid == 0)
                    issue(c + 2, tx, hsrc);         // refill buffer (c+2)%3
            }

            // ---- 8-way reduction + epilogue, two N-halves of 16 cols ----
            const int b = tid >> 2, u = tid & 3;
#pragma unroll 1
            for (int hn = 0; hn < 2; hn++) {
#pragma unroll
                for (int m = 0; m < 4; m++)
#pragma unroll
                    for (int nl = 0; nl < 2; nl++)
#pragma unroll
                        for (int e = 0; e < 4; e++) {
                            int row = 16 * m + G + (e >> 1) * 8;
                            int ch = nl * 8 + 2 * tg + (e & 1);
                            sRed[(w * BD + row) * RED_PITCH + ch] = acc[m][2 * hn + nl][e];
                        }
                __syncthreads();
                float gv[4];
#pragma unroll
                for (int g = 0; g < 4; g++) {
                    float s = 0.0f;
#pragma unroll
                    for (int ww = 0; ww < 8; ww++)
                        s += sRed[(ww * BD + b) * RED_PITCH + 4 * u + g];
                    gv[g] = s + bias[hn][g];
                }
                if (!is_out) {
                    float ig = 1.0f / (1.0f + __expf(-gv[0]));
                    float fg = 1.0f / (1.0f + __expf(-gv[1]));
                    float gg = tanhf(gv[2]);
                    float og = 1.0f / (1.0f + __expf(-gv[3]));
                    float cv = fg * cstate[hn] + ig * gg;
                    cstate[hn] = cv;
                    int jl = 4 * hn + u;
                    // slice-major h store: this CTA owns slice blockIdx.x (2KB)
                    g_h[(t + 1) & 1][((size_t)blockIdx.x * 64 + b) * 8 +
                                     2 * (jl & 3) + (jl >> 2)] =
                        f2tff(og * tanhf(cv));
                } else {
                    float* __restrict__ dst = out + (size_t)(t - 1) * BD * OD;
                    int col = (n0 - NG) + hn * 16 + 4 * u;
                    *(float4*)&dst[(size_t)b * OD + col] =
                        make_float4(gv[0], gv[1], gv[2], gv[3]);
                }
                __syncthreads();
            }
        }

        if (t == T_STEPS) break;

        // ---- pre-issue next step's x-only chunks (0,1) BEFORE barrier ----
        const bool nact = is_out ? true : (t + 1 < T_STEPS);
        if (nact && tid == 0) {
            int txn = (t + 1 < T_STEPS) ? (t + 1) : (T_STEPS - 1);
            asm volatile("fence.proxy.async;" ::: "memory");  // order epilogue STS before bulk overwrite
            issue(0, txn, g_h[0]);
            issue(1, txn, g_h[0]);
        }

        // ---- grid barrier (136 CTAs co-resident) ----
        __syncthreads();
        if (tid == 0) {
            __threadfence();
            atomicAdd(&g_arrive, 1u);
            const unsigned target = (unsigned)(t + 1) * NCTA;
            unsigned v;
            do {
                asm volatile("ld.acquire.gpu.u32 %0, [%1];" : "=r"(v) : "l"(&g_arrive));
            } while (v < target);
        }
        __syncthreads();
    }
}

// ---------------------------------------------------------------------------
extern "C" void kernel_launch(void* const* d_in, const int* in_sizes, int n_in,
                              void* d_out, int out_size)
{
    const float* x     = (const float*)d_in[0];
    const float* W_ih  = (const float*)d_in[1];
    const float* W_hh  = (const float*)d_in[2];
    const float* b_ih  = (const float*)d_in[3];
    const float* b_hh  = (const float*)d_in[4];
    const float* W_out = (const float*)d_in[5];
    const float* b_out = (const float*)d_in[6];
    float* out = (float*)d_out;

    cudaFuncSetAttribute(lstm_kernel,
                         cudaFuncAttributeMaxDynamicSharedMemorySize, SMEM_BYTES);
    prep_kernel<<<1024, 256>>>(x);
    lstm_kernel<<<NCTA, 256, SMEM_BYTES>>>(W_ih, W_hh, b_ih, b_hh, W_out, b_out, out);
}